// round 10
// baseline (speedup 1.0000x reference)
#include <cuda_runtime.h>
#include <math.h>

#define VOCAB 32000
#define NTOK  4096
#define HALF  (VOCAB / 2)        // 16000 floats per half-row
#define NVEC  (HALF / 4)         // 4000 float4 per half-row
#define NSTREAM (NTOK * 2)       // 8192 stream blocks
#define NBLK_TOT (NSTREAM + 1)   // + 1 prep block
#define FIXSCALE 34359738368.0   // 2^35

// Packed accumulator: bits[0:14) arrival count, bits[14:64) fixed-point sum.
__device__ unsigned long long g_acc = 0ULL;

__device__ __forceinline__ void contribute_and_maybe_finish(
    long long ll, float* out)
{
    const unsigned long long val = ((unsigned long long)ll << 14) + 1ULL;
    const unsigned long long old = atomicAdd(&g_acc, val);
    if ((old & 0x3FFFULL) == (unsigned long long)(NBLK_TOT - 1)) {
        const long long tot = (long long)(old + val);
        const long long sumll = (tot - (long long)NBLK_TOT) >> 14;
        out[0] = (float)((double)sumll * (1.0 / FIXSCALE));
        g_acc = 0ULL;   // reset for next graph replay
    }
}

// ---------------------------------------------------------------------------
// bid 0:      prep block — targets, gathers, K1 terms, padding-row cancel.
// bid 1..8192: pure half-row streamers — contribute -base*S_half always.
// ---------------------------------------------------------------------------
__global__ void __launch_bounds__(256) fused_kernel(
    const float* __restrict__ x,
    const void*  __restrict__ target_raw,
    float* __restrict__ out)
{
    const int tid  = threadIdx.x;
    const int lane = tid & 31;
    const int warp = tid >> 5;
    const double base = 0.1 / 31999.0;            // SMOOTHING/(V-1)

    if (blockIdx.x != 0) {
        // ================= pure streaming path =================
        const int sb   = blockIdx.x - 1;
        const int row  = sb >> 1;
        const int half = sb & 1;
        const float4* __restrict__ p = reinterpret_cast<const float4*>(
            x + (size_t)row * VOCAB + (size_t)half * HALF);

        float s = 0.0f;
        #pragma unroll 8
        for (int i = tid; i < NVEC; i += 256) {
            float4 v = __ldcs(&p[i]);
            s += (v.x + v.y) + (v.z + v.w);
        }
        #pragma unroll
        for (int o = 16; o > 0; o >>= 1)
            s += __shfl_xor_sync(0xFFFFFFFFu, s, o);
        __shared__ float wsum[8];
        if (lane == 0) wsum[warp] = s;
        __syncthreads();
        if (warp == 0) {
            float S = (lane < 8) ? wsum[lane] : 0.0f;
            #pragma unroll
            for (int o = 4; o > 0; o >>= 1)
                S += __shfl_xor_sync(0xFFFFFFFFu, S, o);
            if (lane == 0)
                contribute_and_maybe_finish(
                    llrint(-base * (double)S * FIXSCALE), out);
        }
        return;
    }

    // ================= prep block =================
    const int* __restrict__ t32 = (const int*)target_raw;
    const long long* __restrict__ t64 = (const long long*)target_raw;

    __shared__ bool s_is64;
    __shared__ unsigned bitmap[NTOK / 32];   // invalid-row bitmap
    for (int i = tid; i < NTOK / 32; i += 256) bitmap[i] = 0u;
    if (warp == 0) {
        int v = t32[2 * lane + 1];           // odd words: int64 hi OR int32 vals
        unsigned nz = __ballot_sync(0xFFFFFFFFu, v != 0);
        if (lane == 0) s_is64 = (nz == 0);
    }
    __syncthreads();
    const bool is64 = s_is64;

    const double LN_BASE = -12.676045024287623;   // ln(0.1/31999)
    const double LN_CONF = -0.10536051565782628;  // ln(0.9)
    const double K1 = (double)(VOCAB - 2) * base * LN_BASE + 0.9 * LN_CONF;

    // Pass 1: valid-row corrections (per-thread fixed order => deterministic)
    double acc = 0.0;
    for (int r = tid; r < NTOK; r += 256) {
        const long long t = is64 ? t64[r] : (long long)t32[r];
        if (t > 0 && t < VOCAB) {
            const size_t ro = (size_t)r * VOCAB;
            const double x0 = (double)x[ro];
            const double xt = (double)x[ro + (size_t)t];
            acc += K1 + base * (x0 + xt) - 0.9 * xt;
        } else {
            atomicOr(&bitmap[r >> 5], 1u << (r & 31));
        }
    }
    long long fixacc = llrint(acc * FIXSCALE);
    __syncthreads();

    // Pass 2: cancel stream contribution of invalid rows (+base*S_row).
    // Expected count ~0; loop skips empty bitmap words fast.
    __shared__ float wred[8];
    for (int w = 0; w < NTOK / 32; w++) {
        unsigned m = bitmap[w];
        while (m) {
            const int b = __ffs(m) - 1;
            m &= m - 1u;
            const int r = w * 32 + b;
            const float4* __restrict__ p =
                reinterpret_cast<const float4*>(x + (size_t)r * VOCAB);
            float s = 0.0f;
            #pragma unroll 4
            for (int i = tid; i < VOCAB / 4; i += 256) {
                float4 v = p[i];
                s += (v.x + v.y) + (v.z + v.w);
            }
            #pragma unroll
            for (int o = 16; o > 0; o >>= 1)
                s += __shfl_xor_sync(0xFFFFFFFFu, s, o);
            if (lane == 0) wred[warp] = s;
            __syncthreads();
            if (tid == 0) {
                float S = 0.0f;
                #pragma unroll
                for (int k = 0; k < 8; k++) S += wred[k];
                fixacc += llrint(base * (double)S * FIXSCALE);
            }
            __syncthreads();
        }
    }

    // Block-wide integer reduce of fixacc (commutative => deterministic)
    #pragma unroll
    for (int o = 16; o > 0; o >>= 1)
        fixacc += __shfl_xor_sync(0xFFFFFFFFu, fixacc, o);
    __shared__ long long lsum[8];
    if (lane == 0) lsum[warp] = fixacc;
    __syncthreads();
    if (tid == 0) {
        long long tot = 0;
        #pragma unroll
        for (int k = 0; k < 8; k++) tot += lsum[k];
        contribute_and_maybe_finish(tot, out);
    }
}

extern "C" void kernel_launch(void* const* d_in, const int* in_sizes, int n_in,
                              void* d_out, int out_size) {
    const float* model_output = (const float*)d_in[0];
    const void*  target       = (const void*)d_in[1];
    float* out = (float*)d_out;

    fused_kernel<<<NBLK_TOT, 256>>>(model_output, target, out);
}